// round 3
// baseline (speedup 1.0000x reference)
#include <cuda_runtime.h>
#include <cuda_bf16.h>

#define NN 50000
#define EE 1000000
#define IN_DIM 128
#define HID 64
#define NL 4

// ---------------- scratch (static device globals; no allocation) -------------
__device__ float g_h[NN * HID];     // node features (layer input / output)
__device__ float g_hp[NN * HID];    // pre-BN layer output
__device__ float g_A[NN * HID];
__device__ float g_B[NN * HID];
__device__ float g_D[NN * HID];
__device__ float g_E[NN * HID];
__device__ int   g_deg[NN];
__device__ int   g_offs[NN + 1];
__device__ int   g_cursor[NN];
__device__ int   g_csr[EE];         // src node of each edge, sorted by dst
__device__ float g_stats[2 * HID];  // per-channel sum, sumsq

// ---------------- sort edges by dst: hist -> scan -> scatter ------------------
__global__ void k_clear_deg() {
    int i = blockIdx.x * blockDim.x + threadIdx.x;
    if (i < NN) g_deg[i] = 0;
}

__global__ void k_hist(const int* __restrict__ ei) {
    int e = blockIdx.x * blockDim.x + threadIdx.x;
    if (e < EE) {
        int d = ei[EE + e];
        if (d >= 0 && d < NN) atomicAdd(&g_deg[d], 1);
    }
}

__global__ void k_scan() {  // single block, 1024 threads
    __shared__ int wsum[32];
    __shared__ int carry_sh;
    int t = threadIdx.x;
    if (t == 0) carry_sh = 0;
    __syncthreads();
    for (int base = 0; base < NN; base += 1024) {
        int i = base + t;
        int v = (i < NN) ? g_deg[i] : 0;
        int x = v;
        #pragma unroll
        for (int o = 1; o < 32; o <<= 1) {
            int y = __shfl_up_sync(0xffffffffu, x, o);
            if ((t & 31) >= o) x += y;
        }
        if ((t & 31) == 31) wsum[t >> 5] = x;
        __syncthreads();
        if (t < 32) {
            int w = wsum[t];
            #pragma unroll
            for (int o = 1; o < 32; o <<= 1) {
                int y = __shfl_up_sync(0xffffffffu, w, o);
                if (t >= o) w += y;
            }
            wsum[t] = w;
        }
        __syncthreads();
        int incl = x + ((t >= 32) ? wsum[(t >> 5) - 1] : 0);
        int carry = carry_sh;
        if (i < NN) {
            g_offs[i + 1]  = carry + incl;
            g_cursor[i]    = carry + incl - v;  // exclusive prefix = start
        }
        __syncthreads();
        if (t == 0) carry_sh = carry + wsum[31];
        __syncthreads();
    }
    if (t == 0) g_offs[0] = 0;
}

__global__ void k_scatter(const int* __restrict__ ei) {
    int e = blockIdx.x * blockDim.x + threadIdx.x;
    if (e < EE) {
        int d = ei[EE + e];
        int s = ei[e];
        if (d >= 0 && d < NN) {
            int pos = atomicAdd(&g_cursor[d], 1);
            if (pos >= 0 && pos < EE) g_csr[pos] = s;
        }
    }
}

// ---------------- embed: h = feature @ emb_w + emb_b -------------------------
// 256 threads, 32 rows/block; static smem: W[128][64] 32KB + X[32][128] 16KB
__global__ __launch_bounds__(256) void k_embed(const float* __restrict__ X,
                                               const float* __restrict__ W,
                                               const float* __restrict__ bias) {
    __shared__ float Ws[IN_DIM * HID];   // 8192 floats
    __shared__ float Xs[32 * IN_DIM];    // 4096 floats
    int t = threadIdx.x;
    int m0 = blockIdx.x * 32;
    for (int idx = t; idx < IN_DIM * HID; idx += 256) Ws[idx] = W[idx];
    for (int idx = t; idx < 32 * IN_DIM; idx += 256) {
        int m = m0 + (idx >> 7);
        Xs[idx] = (m < NN) ? X[m * IN_DIM + (idx & 127)] : 0.f;
    }
    __syncthreads();
    int tx = t & 31, ty = t >> 5;   // tx: 32 col-pairs, ty: 8 row groups
    int c0 = tx * 2, r0 = ty * 4;   // 4 rows x 2 cols per thread
    float acc[4][2];
    #pragma unroll
    for (int i = 0; i < 4; i++) { acc[i][0] = 0.f; acc[i][1] = 0.f; }
    #pragma unroll 8
    for (int k = 0; k < IN_DIM; k++) {
        float2 w = *(const float2*)&Ws[k * HID + c0];
        #pragma unroll
        for (int i = 0; i < 4; i++) {
            float x = Xs[(r0 + i) * IN_DIM + k];
            acc[i][0] += x * w.x;
            acc[i][1] += x * w.y;
        }
    }
    float b0 = bias[c0], b1 = bias[c0 + 1];
    #pragma unroll
    for (int i = 0; i < 4; i++) {
        int m = m0 + r0 + i;
        if (m < NN) {
            g_h[m * HID + c0]     = acc[i][0] + b0;
            g_h[m * HID + c0 + 1] = acc[i][1] + b1;
        }
    }
}

// ---------------- layer linears --------------------------------------------
// gridDim.y = 2: pair 0 -> (A,B), pair 1 -> (D,E). 64 rows x 128 cols per block.
// static smem: Ws[64][128] 32KB + Xs[64][64] 16KB = 48KB
__global__ __launch_bounds__(256) void k_abde(
    const float* __restrict__ Aw, const float* __restrict__ Bw,
    const float* __restrict__ Dw, const float* __restrict__ Ew,
    const float* __restrict__ Ab, const float* __restrict__ Bb,
    const float* __restrict__ Db, const float* __restrict__ Eb) {
    __shared__ float Ws[HID * 128];  // k-major, 2 matrices side by side
    __shared__ float Xs[64 * HID];
    int t = threadIdx.x;
    int m0 = blockIdx.x * 64;
    int pair = blockIdx.y;           // 0: A,B   1: D,E
    const float* W0 = pair ? Dw : Aw;
    const float* W1 = pair ? Ew : Bw;
    for (int idx = t; idx < HID * 128; idx += 256) {
        int k = idx >> 7, c = idx & 127;
        Ws[idx] = (c < 64) ? W0[k * HID + c] : W1[k * HID + (c - 64)];
    }
    for (int idx = t; idx < 64 * HID; idx += 256) {
        int m = m0 + (idx >> 6);
        Xs[idx] = (m < NN) ? g_h[m * HID + (idx & 63)] : 0.f;
    }
    __syncthreads();
    int tx = t & 31, ty = t >> 5;
    int c0 = tx * 4, r0 = ty * 8;    // 8 rows x 4 cols per thread
    float acc[8][4];
    #pragma unroll
    for (int i = 0; i < 8; i++)
        #pragma unroll
        for (int j = 0; j < 4; j++) acc[i][j] = 0.f;
    #pragma unroll 8
    for (int k = 0; k < HID; k++) {
        float4 w = *(const float4*)&Ws[k * 128 + c0];
        #pragma unroll
        for (int i = 0; i < 8; i++) {
            float x = Xs[(r0 + i) * HID + k];
            acc[i][0] += x * w.x; acc[i][1] += x * w.y;
            acc[i][2] += x * w.z; acc[i][3] += x * w.w;
        }
    }
    int sel = c0 >> 6, cc = c0 & 63;
    float* Y = pair ? (sel ? g_E : g_D) : (sel ? g_B : g_A);
    const float* bb = pair ? (sel ? Eb : Db) : (sel ? Bb : Ab);
    float bias[4];
    #pragma unroll
    for (int j = 0; j < 4; j++) bias[j] = bb[cc + j];
    #pragma unroll
    for (int i = 0; i < 8; i++) {
        int m = m0 + r0 + i;
        if (m < NN) {
            #pragma unroll
            for (int j = 0; j < 4; j++) Y[m * HID + cc + j] = acc[i][j] + bias[j];
        }
    }
}

// ---------------- edge aggregation (atomic-free): warp per dst node ----------
__global__ __launch_bounds__(256) void k_agg() {
    int gw = (blockIdx.x * blockDim.x + threadIdx.x) >> 5;
    if (gw >= NN) return;
    int lane = threadIdx.x & 31;
    int s0 = g_offs[gw], s1 = g_offs[gw + 1];
    int off = gw * HID + lane * 2;
    float2 el = *(const float2*)&g_E[off];
    float nx = 0.f, ny = 0.f, dx = 0.f, dy = 0.f;
    for (int k = s0; k < s1; k++) {
        int s = g_csr[k];
        float2 dd = *(const float2*)&g_D[s * HID + lane * 2];
        float2 bb = *(const float2*)&g_B[s * HID + lane * 2];
        float sx = 1.f / (1.f + __expf(-(dd.x + el.x)));
        float sy = 1.f / (1.f + __expf(-(dd.y + el.y)));
        nx += sx * bb.x; ny += sy * bb.y;
        dx += sx;        dy += sy;
    }
    float2 aa = *(const float2*)&g_A[off];
    float2 o;
    o.x = aa.x + nx / (dx + 1e-6f);
    o.y = aa.y + ny / (dy + 1e-6f);
    *(float2*)&g_hp[off] = o;
}

// ---------------- BN stats + BN/ReLU/residual --------------------------------
__global__ void k_clear_stats() {
    int t = threadIdx.x;
    if (t < 2 * HID) g_stats[t] = 0.f;
}

__global__ __launch_bounds__(256) void k_stats() {
    __shared__ float ss[256], sq[256];
    int t = threadIdx.x;
    int c = t & 63, rgrp = t >> 6;  // 4 row groups
    float s = 0.f, q = 0.f;
    for (int r = blockIdx.x * 4 + rgrp; r < NN; r += gridDim.x * 4) {
        float v = g_hp[r * HID + c];
        s += v; q += v * v;
    }
    ss[t] = s; sq[t] = q;
    __syncthreads();
    if (t < 64) {
        s = ss[t] + ss[t + 64] + ss[t + 128] + ss[t + 192];
        q = sq[t] + sq[t + 64] + sq[t + 128] + sq[t + 192];
        atomicAdd(&g_stats[t], s);
        atomicAdd(&g_stats[HID + t], q);
    }
}

__global__ __launch_bounds__(256) void k_bn(const float* __restrict__ gamma,
                                            const float* __restrict__ beta,
                                            float* __restrict__ out,
                                            int write_out) {
    int idx = blockIdx.x * blockDim.x + threadIdx.x;
    if (idx >= NN * HID) return;
    int c = idx & 63;
    const float invN = 1.f / (float)NN;
    float mu  = g_stats[c] * invN;
    float var = g_stats[HID + c] * invN - mu * mu;
    float xn = (g_hp[idx] - mu) * rsqrtf(var + 1e-5f);
    float v = gamma[c] * xn + beta[c];
    v = fmaxf(v, 0.f);
    float r = g_h[idx] + v;
    g_h[idx] = r;                 // next layer input (residual applied)
    if (write_out) out[idx] = r;  // final layer: also write harness output
}

// ---------------- launch ------------------------------------------------------
extern "C" void kernel_launch(void* const* d_in, const int* in_sizes, int n_in,
                              void* d_out, int out_size) {
    const float* feature = (const float*)d_in[0];
    const int*   ei      = (const int*)d_in[1];     // int32! (JAX x64 disabled)
    const float* emb_w   = (const float*)d_in[2];
    const float* emb_b   = (const float*)d_in[3];
    const float* Aw      = (const float*)d_in[4];
    const float* Ab      = (const float*)d_in[5];
    const float* Bw      = (const float*)d_in[6];
    const float* Bb      = (const float*)d_in[7];
    const float* Dw      = (const float*)d_in[8];
    const float* Db      = (const float*)d_in[9];
    const float* Ew      = (const float*)d_in[10];
    const float* Eb      = (const float*)d_in[11];
    const float* gamma   = (const float*)d_in[12];
    const float* beta    = (const float*)d_in[13];
    float* out = (float*)d_out;

    // one-time per launch: CSR by dst
    k_clear_deg<<<(NN + 255) / 256, 256>>>();
    k_hist<<<(EE + 255) / 256, 256>>>(ei);
    k_scan<<<1, 1024>>>();
    k_scatter<<<(EE + 255) / 256, 256>>>(ei);

    k_embed<<<(NN + 31) / 32, 256>>>(feature, emb_w, emb_b);

    for (int l = 0; l < NL; l++) {
        dim3 gabde((NN + 63) / 64, 2);
        k_abde<<<gabde, 256>>>(
            Aw + l * HID * HID, Bw + l * HID * HID,
            Dw + l * HID * HID, Ew + l * HID * HID,
            Ab + l * HID, Bb + l * HID, Db + l * HID, Eb + l * HID);
        k_agg<<<(NN * 32 + 255) / 256, 256>>>();
        k_clear_stats<<<1, 128>>>();
        k_stats<<<512, 256>>>();
        k_bn<<<(NN * HID + 255) / 256, 256>>>(gamma + l * HID, beta + l * HID,
                                              out, (l == NL - 1) ? 1 : 0);
    }
}

// round 4
// speedup vs baseline: 1.1827x; 1.1827x over previous
#include <cuda_runtime.h>
#include <cuda_bf16.h>

#define NN 50000
#define EE 1000000
#define IN_DIM 128
#define HID 64
#define NL 4

// ---------------- scratch (static device globals; no allocation) -------------
__device__ float    g_h[NN * HID];     // node features (layer input / output)
__device__ float    g_hp[NN * HID];    // pre-BN layer output
__device__ float    g_A[NN * HID];
__device__ float    g_E[NN * HID];
__device__ unsigned g_Bb[NN * 32];     // Bh rows, bf16x2 packed (64 ch -> 32 words)
__device__ unsigned g_Db[NN * 32];     // Dh rows, bf16x2 packed
__device__ int      g_deg[NN];
__device__ int      g_offs[NN + 1];
__device__ int      g_cursor[NN];
__device__ int      g_csr[EE];         // src node of each edge, sorted by dst
__device__ float    g_stats[2 * HID];  // per-channel sum, sumsq

__device__ __forceinline__ unsigned pack_bf16x2(float a, float b) {
    __nv_bfloat162 h = __floats2bfloat162_rn(a, b);
    return *reinterpret_cast<unsigned*>(&h);
}
__device__ __forceinline__ float2 unpack_bf16x2(unsigned u) {
    __nv_bfloat162 h = *reinterpret_cast<__nv_bfloat162*>(&u);
    return __bfloat1622float2(h);
}

// ---------------- sort edges by dst: hist -> scan -> scatter ------------------
__global__ void k_clear_deg() {
    int i = blockIdx.x * blockDim.x + threadIdx.x;
    if (i < NN) g_deg[i] = 0;
}

__global__ void k_hist(const int* __restrict__ ei) {
    int e = blockIdx.x * blockDim.x + threadIdx.x;
    if (e < EE) {
        int d = ei[EE + e];
        if (d >= 0 && d < NN) atomicAdd(&g_deg[d], 1);
    }
}

__global__ void k_scan() {  // single block, 1024 threads
    __shared__ int wsum[32];
    __shared__ int carry_sh;
    int t = threadIdx.x;
    if (t == 0) carry_sh = 0;
    __syncthreads();
    for (int base = 0; base < NN; base += 1024) {
        int i = base + t;
        int v = (i < NN) ? g_deg[i] : 0;
        int x = v;
        #pragma unroll
        for (int o = 1; o < 32; o <<= 1) {
            int y = __shfl_up_sync(0xffffffffu, x, o);
            if ((t & 31) >= o) x += y;
        }
        if ((t & 31) == 31) wsum[t >> 5] = x;
        __syncthreads();
        if (t < 32) {
            int w = wsum[t];
            #pragma unroll
            for (int o = 1; o < 32; o <<= 1) {
                int y = __shfl_up_sync(0xffffffffu, w, o);
                if (t >= o) w += y;
            }
            wsum[t] = w;
        }
        __syncthreads();
        int incl = x + ((t >= 32) ? wsum[(t >> 5) - 1] : 0);
        int carry = carry_sh;
        if (i < NN) {
            g_offs[i + 1]  = carry + incl;
            g_cursor[i]    = carry + incl - v;  // exclusive prefix = start
        }
        __syncthreads();
        if (t == 0) carry_sh = carry + wsum[31];
        __syncthreads();
    }
    if (t == 0) g_offs[0] = 0;
}

__global__ void k_scatter(const int* __restrict__ ei) {
    int e = blockIdx.x * blockDim.x + threadIdx.x;
    if (e < EE) {
        int d = ei[EE + e];
        int s = ei[e];
        if (d >= 0 && d < NN) {
            int pos = atomicAdd(&g_cursor[d], 1);
            if (pos >= 0 && pos < EE) g_csr[pos] = s;
        }
    }
}

// ---------------- embed: h = feature @ emb_w + emb_b -------------------------
__global__ __launch_bounds__(256) void k_embed(const float* __restrict__ X,
                                               const float* __restrict__ W,
                                               const float* __restrict__ bias) {
    __shared__ float Ws[IN_DIM * HID];   // 32KB
    __shared__ float Xs[32 * IN_DIM];    // 16KB
    int t = threadIdx.x;
    int m0 = blockIdx.x * 32;
    for (int idx = t; idx < IN_DIM * HID; idx += 256) Ws[idx] = W[idx];
    for (int idx = t; idx < 32 * IN_DIM; idx += 256) {
        int m = m0 + (idx >> 7);
        Xs[idx] = (m < NN) ? X[m * IN_DIM + (idx & 127)] : 0.f;
    }
    __syncthreads();
    int tx = t & 31, ty = t >> 5;
    int c0 = tx * 2, r0 = ty * 4;
    float acc[4][2];
    #pragma unroll
    for (int i = 0; i < 4; i++) { acc[i][0] = 0.f; acc[i][1] = 0.f; }
    #pragma unroll 8
    for (int k = 0; k < IN_DIM; k++) {
        float2 w = *(const float2*)&Ws[k * HID + c0];
        #pragma unroll
        for (int i = 0; i < 4; i++) {
            float x = Xs[(r0 + i) * IN_DIM + k];
            acc[i][0] += x * w.x;
            acc[i][1] += x * w.y;
        }
    }
    float b0 = bias[c0], b1 = bias[c0 + 1];
    #pragma unroll
    for (int i = 0; i < 4; i++) {
        int m = m0 + r0 + i;
        if (m < NN) {
            g_h[m * HID + c0]     = acc[i][0] + b0;
            g_h[m * HID + c0 + 1] = acc[i][1] + b1;
        }
    }
}

// ---------------- layer linears: 64 rows x 256 cols per block ----------------
// Two column halves (A|B then D|E) reusing a 48KB static smem footprint.
// 8 rows x 4 cols per thread per half. X loads are warp-broadcast.
__global__ __launch_bounds__(256) void k_abde(
    const float* __restrict__ Aw, const float* __restrict__ Bw,
    const float* __restrict__ Dw, const float* __restrict__ Ew,
    const float* __restrict__ Ab, const float* __restrict__ Bb,
    const float* __restrict__ Db, const float* __restrict__ Eb) {
    __shared__ float Ws[HID * 128];   // 32KB, k-major: 128 cols of current half
    __shared__ float Xs[64 * HID];    // 16KB, row-major
    int t = threadIdx.x;
    int m0 = blockIdx.x * 64;

    // load X tile (float4, coalesced)
    for (int idx = t; idx < 64 * (HID / 4); idx += 256) {
        int m = m0 + idx / (HID / 4);
        float4 v = make_float4(0.f, 0.f, 0.f, 0.f);
        if (m < NN) v = *(const float4*)&g_h[m * HID + (idx % (HID / 4)) * 4];
        *(float4*)&Xs[idx * 4] = v;
    }

    const int tx = t & 31, ty = t >> 5;
    const int c0 = tx * 4, r0 = ty * 8;

    #pragma unroll
    for (int half = 0; half < 2; half++) {
        // load weight half: cols [half*128, half*128+128) of the 256-wide concat
        for (int idx = t; idx < HID * 128; idx += 256) {
            int k = idx >> 7, c = idx & 127;
            int gc = half * 128 + c;
            int sel = gc >> 6;
            const float* W = (sel == 0) ? Aw : (sel == 1) ? Bw : (sel == 2) ? Dw : Ew;
            Ws[idx] = W[k * HID + (gc & 63)];
        }
        __syncthreads();

        float acc[8][4];
        #pragma unroll
        for (int i = 0; i < 8; i++)
            #pragma unroll
            for (int j = 0; j < 4; j++) acc[i][j] = 0.f;

        #pragma unroll 4
        for (int k0 = 0; k0 < HID; k0 += 4) {
            float4 xv[8];
            #pragma unroll
            for (int i = 0; i < 8; i++)
                xv[i] = *(const float4*)&Xs[(r0 + i) * HID + k0];
            #pragma unroll
            for (int kk = 0; kk < 4; kk++) {
                float4 w = *(const float4*)&Ws[(k0 + kk) * 128 + c0];
                #pragma unroll
                for (int i = 0; i < 8; i++) {
                    float x = (kk == 0) ? xv[i].x : (kk == 1) ? xv[i].y
                            : (kk == 2) ? xv[i].z : xv[i].w;
                    acc[i][0] += x * w.x; acc[i][1] += x * w.y;
                    acc[i][2] += x * w.z; acc[i][3] += x * w.w;
                }
            }
        }

        int gc0 = half * 128 + c0;
        int sel = gc0 >> 6, cc = gc0 & 63;
        const float* bp = (sel == 0) ? Ab : (sel == 1) ? Bb : (sel == 2) ? Db : Eb;
        float b0 = bp[cc], b1 = bp[cc + 1], b2 = bp[cc + 2], b3 = bp[cc + 3];

        if (sel == 0 || sel == 3) {            // A or E: fp32
            float* Y = (sel == 0) ? g_A : g_E;
            #pragma unroll
            for (int i = 0; i < 8; i++) {
                int m = m0 + r0 + i;
                if (m < NN) {
                    float4 v = make_float4(acc[i][0] + b0, acc[i][1] + b1,
                                           acc[i][2] + b2, acc[i][3] + b3);
                    *(float4*)&Y[m * HID + cc] = v;
                }
            }
        } else {                               // B or D: bf16x2 packed
            unsigned* Y = (sel == 1) ? g_Bb : g_Db;
            #pragma unroll
            for (int i = 0; i < 8; i++) {
                int m = m0 + r0 + i;
                if (m < NN) {
                    uint2 pk;
                    pk.x = pack_bf16x2(acc[i][0] + b0, acc[i][1] + b1);
                    pk.y = pack_bf16x2(acc[i][2] + b2, acc[i][3] + b3);
                    *(uint2*)&Y[m * 32 + (cc >> 1)] = pk;
                }
            }
        }
        __syncthreads();   // before Ws reuse / exit
    }
}

// ---------------- edge aggregation: warp per dst node, bf16 gathers ----------
__global__ __launch_bounds__(256) void k_agg() {
    int gw = (blockIdx.x * blockDim.x + threadIdx.x) >> 5;
    if (gw >= NN) return;
    int lane = threadIdx.x & 31;
    int s0 = g_offs[gw], s1 = g_offs[gw + 1];
    int off = gw * HID + lane * 2;
    float2 el = *(const float2*)&g_E[off];
    float nx = 0.f, ny = 0.f, dx = 0.f, dy = 0.f;
    int k = s0;
    for (; k + 1 < s1; k += 2) {
        int sa = g_csr[k], sb = g_csr[k + 1];
        unsigned ua_d = g_Db[sa * 32 + lane];
        unsigned ua_b = g_Bb[sa * 32 + lane];
        unsigned ub_d = g_Db[sb * 32 + lane];
        unsigned ub_b = g_Bb[sb * 32 + lane];
        float2 da = unpack_bf16x2(ua_d), ba = unpack_bf16x2(ua_b);
        float2 db = unpack_bf16x2(ub_d), bb = unpack_bf16x2(ub_b);
        float s0x = 1.f / (1.f + __expf(-(da.x + el.x)));
        float s0y = 1.f / (1.f + __expf(-(da.y + el.y)));
        float s1x = 1.f / (1.f + __expf(-(db.x + el.x)));
        float s1y = 1.f / (1.f + __expf(-(db.y + el.y)));
        nx += s0x * ba.x + s1x * bb.x;
        ny += s0y * ba.y + s1y * bb.y;
        dx += s0x + s1x;
        dy += s0y + s1y;
    }
    if (k < s1) {
        int sa = g_csr[k];
        float2 da = unpack_bf16x2(g_Db[sa * 32 + lane]);
        float2 ba = unpack_bf16x2(g_Bb[sa * 32 + lane]);
        float sx = 1.f / (1.f + __expf(-(da.x + el.x)));
        float sy = 1.f / (1.f + __expf(-(da.y + el.y)));
        nx += sx * ba.x; ny += sy * ba.y;
        dx += sx;        dy += sy;
    }
    float2 aa = *(const float2*)&g_A[off];
    float2 o;
    o.x = aa.x + nx / (dx + 1e-6f);
    o.y = aa.y + ny / (dy + 1e-6f);
    *(float2*)&g_hp[off] = o;
}

// ---------------- BN stats + BN/ReLU/residual --------------------------------
__global__ void k_clear_stats() {
    int t = threadIdx.x;
    if (t < 2 * HID) g_stats[t] = 0.f;
}

__global__ __launch_bounds__(256) void k_stats() {
    __shared__ float ss[256], sq[256];
    int t = threadIdx.x;
    int c = t & 63, rgrp = t >> 6;  // 4 row groups
    float s = 0.f, q = 0.f;
    for (int r = blockIdx.x * 4 + rgrp; r < NN; r += gridDim.x * 4) {
        float v = g_hp[r * HID + c];
        s += v; q += v * v;
    }
    ss[t] = s; sq[t] = q;
    __syncthreads();
    if (t < 64) {
        s = ss[t] + ss[t + 64] + ss[t + 128] + ss[t + 192];
        q = sq[t] + sq[t + 64] + sq[t + 128] + sq[t + 192];
        atomicAdd(&g_stats[t], s);
        atomicAdd(&g_stats[HID + t], q);
    }
}

__global__ __launch_bounds__(256) void k_bn(const float* __restrict__ gamma,
                                            const float* __restrict__ beta,
                                            float* __restrict__ out,
                                            int write_out) {
    int idx = blockIdx.x * blockDim.x + threadIdx.x;
    if (idx >= NN * HID) return;
    int c = idx & 63;
    const float invN = 1.f / (float)NN;
    float mu  = g_stats[c] * invN;
    float var = g_stats[HID + c] * invN - mu * mu;
    float xn = (g_hp[idx] - mu) * rsqrtf(var + 1e-5f);
    float v = gamma[c] * xn + beta[c];
    v = fmaxf(v, 0.f);
    float r = g_h[idx] + v;
    g_h[idx] = r;                 // next layer input (residual applied)
    if (write_out) out[idx] = r;  // final layer: also write harness output
}

// ---------------- launch ------------------------------------------------------
extern "C" void kernel_launch(void* const* d_in, const int* in_sizes, int n_in,
                              void* d_out, int out_size) {
    const float* feature = (const float*)d_in[0];
    const int*   ei      = (const int*)d_in[1];     // int32 (JAX x64 disabled)
    const float* emb_w   = (const float*)d_in[2];
    const float* emb_b   = (const float*)d_in[3];
    const float* Aw      = (const float*)d_in[4];
    const float* Ab      = (const float*)d_in[5];
    const float* Bw      = (const float*)d_in[6];
    const float* Bb      = (const float*)d_in[7];
    const float* Dw      = (const float*)d_in[8];
    const float* Db      = (const float*)d_in[9];
    const float* Ew      = (const float*)d_in[10];
    const float* Eb      = (const float*)d_in[11];
    const float* gamma   = (const float*)d_in[12];
    const float* beta    = (const float*)d_in[13];
    float* out = (float*)d_out;

    // one-time per launch: CSR by dst
    k_clear_deg<<<(NN + 255) / 256, 256>>>();
    k_hist<<<(EE + 255) / 256, 256>>>(ei);
    k_scan<<<1, 1024>>>();
    k_scatter<<<(EE + 255) / 256, 256>>>(ei);

    k_embed<<<(NN + 31) / 32, 256>>>(feature, emb_w, emb_b);

    for (int l = 0; l < NL; l++) {
        k_abde<<<(NN + 63) / 64, 256>>>(
            Aw + l * HID * HID, Bw + l * HID * HID,
            Dw + l * HID * HID, Ew + l * HID * HID,
            Ab + l * HID, Bb + l * HID, Db + l * HID, Eb + l * HID);
        k_agg<<<(NN * 32 + 255) / 256, 256>>>();
        k_clear_stats<<<1, 128>>>();
        k_stats<<<512, 256>>>();
        k_bn<<<(NN * HID + 255) / 256, 256>>>(gamma + l * HID, beta + l * HID,
                                              out, (l == NL - 1) ? 1 : 0);
    }
}